// round 15
// baseline (speedup 1.0000x reference)
#include <cuda_runtime.h>
#include <math.h>

#define HID   512
#define VOCAB 50000
#define BATCH 64
#define SRC   50
#define STEPS 31
#define VT    128                 /* vocab tile per logits block */
#define NLOG  391                 /* ceil(50000/128) */
#define KT    32                  /* k tile */
#define NTILE (HID / KT)          /* 16 */
#define NEG_INF (-3.402823466e38f)

typedef unsigned long long ull;

// ---------------- persistent device state (no allocations allowed) ----------
__device__ __align__(16) float g_h[BATCH * HID];      // post-attention hidden (carry)
__device__ __align__(16) float g_c[BATCH * HID];      // post-attention cell   (carry)
__device__ __align__(16) float g_hrnn[BATCH * HID];   // raw LSTM outputs this step
__device__ __align__(16) float g_crnn[BATCH * HID];
__device__ int   g_tok[BATCH];
__device__ float g_pmax[NLOG * 2 * BATCH];            // 2 vocab-half partials per block
__device__ int   g_pidx[NLOG * 2 * BATCH];
__device__ int   g_done;

// ---------------- f32x2 packed-FMA helpers (Blackwell dual fp32 pipe) -------
__device__ __forceinline__ ull pack2(float x, float y) {
    ull r; asm("mov.b64 %0, {%1,%2};" : "=l"(r) : "f"(x), "f"(y)); return r;
}
__device__ __forceinline__ void unpack2(ull a, float& x, float& y) {
    asm("mov.b64 {%0,%1}, %2;" : "=f"(x), "=f"(y) : "l"(a));
}
__device__ __forceinline__ ull fma2(ull a, ull b, ull c) {
    ull d; asm("fma.rn.f32x2 %0, %1, %2, %3;" : "=l"(d) : "l"(a), "l"(b), "l"(c)); return d;
}
__device__ __forceinline__ float sigmoidf_(float x) { return 1.f / (1.f + expf(-x)); }

// ---------------- init ------------------------------------------------------
__global__ void k_init(const float* __restrict__ h0, const float* __restrict__ c0,
                       const int* __restrict__ t0) {
    int tid = blockIdx.x * blockDim.x + threadIdx.x;
    for (int i = tid; i < BATCH * HID; i += blockDim.x * gridDim.x) {
        g_h[i] = h0[i];
        g_c[i] = c0[i];
    }
    if (tid < BATCH) g_tok[tid] = t0[tid];
    if (tid == 0) g_done = 0;
}

// ---------------- LSTM cell (unchanged from R14, measured 37.3us) -----------
__global__ void __launch_bounds__(512) k_lstm(const float* __restrict__ embed,
                       const float* __restrict__ w_ih,
                       const float* __restrict__ w_hh,
                       const float* __restrict__ b_ih,
                       const float* __restrict__ b_hh) {
    __shared__ ull   wi_t[16][KT + 2];   // [row][k] splatted pairs, stride 34 ull
    __shared__ ull   wh_t[16][KT + 2];
    __shared__ ull   x_p [32][KT + 2];   // [bpair][k] (x[2bp][k], x[2bp+1][k])
    __shared__ ull   h_p [32][KT + 2];
    __shared__ float gate_sm[16][66];
    __shared__ int   tok_sm[BATCH];

    const int tid = threadIdx.x;
    const int hd0 = blockIdx.x * 4;
    if (tid < BATCH) tok_sm[tid] = g_tok[tid];

    const int rr = tid & 15;            // gate row: g*4 + dloc
    const int bq = tid >> 4;            // 0..31 batch pair
    const int jrow = (rr >> 2) * HID + hd0 + (rr & 3);
    const float bias = b_ih[jrow] + b_hh[jrow];
    ull acc = pack2(bias, bias);

    const int w_kp = tid & 15;          // 16 k-pairs (coalesced along k)
    const int w_rr = (tid >> 4) & 15;
    const int w_m  = tid >> 8;
    const int w_j  = (w_rr >> 2) * HID + hd0 + (w_rr & 3);
    const float* wsrc = (w_m ? w_hh : w_ih) + (size_t)w_j * HID;
    const int f_bp = tid & 31;          // batch pair
    const int f_kq = (tid >> 5) & 7;    // 8 groups of 4 k
    __syncthreads();                    // tok_sm visible

    const float *s0, *s1;
    if (w_m) { s0 = g_h + (size_t)(2 * f_bp) * HID;
               s1 = g_h + (size_t)(2 * f_bp + 1) * HID; }
    else     { s0 = embed + (size_t)tok_sm[2 * f_bp]     * HID;
               s1 = embed + (size_t)tok_sm[2 * f_bp + 1] * HID; }

    float2 wp = *(const float2*)(wsrc + 2 * w_kp);
    float4 pa = *(const float4*)(s0 + 4 * f_kq);
    float4 pb = *(const float4*)(s1 + 4 * f_kq);

    for (int kt = 0; kt < NTILE; kt++) {
        __syncthreads();
        {
            ull* wt = (w_m ? &wh_t[0][0] : &wi_t[0][0]) + w_rr * (KT + 2);
            ulonglong2 wv; wv.x = pack2(wp.x, wp.x); wv.y = pack2(wp.y, wp.y);
            *(ulonglong2*)&wt[2 * w_kp] = wv;
        }
        {
            ull* xt = (w_m ? &h_p[0][0] : &x_p[0][0]) + f_bp * (KT + 2);
            ulonglong2 v0; v0.x = pack2(pa.x, pb.x); v0.y = pack2(pa.y, pb.y);
            ulonglong2 v1; v1.x = pack2(pa.z, pb.z); v1.y = pack2(pa.w, pb.w);
            *(ulonglong2*)&xt[4 * f_kq]     = v0;
            *(ulonglong2*)&xt[4 * f_kq + 2] = v1;
        }
        __syncthreads();
        if (kt + 1 < NTILE) {
            const int k0n = (kt + 1) * KT;
            wp = *(const float2*)(wsrc + k0n + 2 * w_kp);
            pa = *(const float4*)(s0 + k0n + 4 * f_kq);
            pb = *(const float4*)(s1 + k0n + 4 * f_kq);
        }
#pragma unroll
        for (int k = 0; k < KT; k += 2) {
            ulonglong2 wi2 = *(const ulonglong2*)&wi_t[rr][k];
            ulonglong2 wh2 = *(const ulonglong2*)&wh_t[rr][k];
            ulonglong2 xv2 = *(const ulonglong2*)&x_p[bq][k];
            ulonglong2 hv2 = *(const ulonglong2*)&h_p[bq][k];
            acc = fma2(wi2.x, xv2.x, acc);
            acc = fma2(wh2.x, hv2.x, acc);
            acc = fma2(wi2.y, xv2.y, acc);
            acc = fma2(wh2.y, hv2.y, acc);
        }
    }
    *(ull*)&gate_sm[rr][2 * bq] = acc;
    __syncthreads();
    if (tid < 256) {
        int dd = tid >> 6, b = tid & 63;
        float ig = sigmoidf_(gate_sm[dd][b]);
        float fg = sigmoidf_(gate_sm[4 + dd][b]);
        float gg = tanhf(gate_sm[8 + dd][b]);
        float og = sigmoidf_(gate_sm[12 + dd][b]);
        int idx = b * HID + hd0 + dd;
        float cn = fg * g_c[idx] + ig * gg;
        g_crnn[idx] = cn;
        g_hrnn[idx] = og * tanhf(cn);
    }
}

// ---------------- fused: logits(+argmax partials) | attention | final argmax
// Logits warp tile reshaped to 2 vocab x 8 batch-pairs: 1 e-LDS.128 (the only
// non-broadcast read) + 4 broadcast h-LDS.128 per k feed 16 fma2.
struct SmLogits { ull e[2][KT][64]; float h[KT][64]; };    // 32KB + 8KB
struct SmAttn   { float vv[HID]; float sc[64]; float isum; };
struct SmAmax   { float sv[256]; int si[256]; };
union SmU { SmLogits l; SmAttn a; SmAmax m; };

__global__ void __launch_bounds__(256) k_fused(
        const float* __restrict__ embed, const float* __restrict__ fc_bias,
        const float* __restrict__ enc, float* __restrict__ out_step,
        float* __restrict__ out_tok, int step, int write_tok) {
    __shared__ SmU sm;
    __shared__ int s_last;

    const int tid  = threadIdx.x;
    const int lane = tid & 31;
    const int warp = tid >> 5;
    const int bid  = blockIdx.x;

    if (bid < NLOG) {
        // ============ logits: warp = 64 vocab (one half) x 16 batches ========
        const int vbase = bid * VT;
        const int vhalf = warp & 1;
        const int bq4   = warp >> 1;                 // 0..3
        const int v0    = vbase + 64 * vhalf + 2 * lane;
        const int bb    = 16 * bq4;                  // first batch of warp
        const int gval  = (v0 + 2 <= VOCAB);

        float bz0 = gval ? fc_bias[v0]     : 0.f;
        float bz1 = gval ? fc_bias[v0 + 1] : 0.f;
        ull acc0[8], acc1[8];                        // [batch pair], v0 and v0+1
#pragma unroll
        for (int j = 0; j < 8; j++) { acc0[j] = pack2(bz0, bz0); acc1[j] = pack2(bz1, bz1); }

        const int fv  = tid & 127;   // fill vocab row
        const int fkh = tid >> 7;    // 0/1: which 16-k half
        const int fb  = tid & 63;    // fill batch
        const int fkq = tid >> 6;    // 0..3: 8-k group

        for (int k0 = 0; k0 < HID; k0 += KT) {
            {   // embed -> dup'd [half][k][v]
                const int gv = vbase + fv;
                ull* dst = &sm.l.e[fv >> 6][fkh * 16][fv & 63];
                if (gv < VOCAB) {
                    const float4* src = (const float4*)(embed + (size_t)gv * HID + k0 + fkh * 16);
#pragma unroll
                    for (int jj = 0; jj < 4; jj++) {
                        float4 f = src[jj];
                        dst[(4 * jj + 0) * 64] = pack2(f.x, f.x);
                        dst[(4 * jj + 1) * 64] = pack2(f.y, f.y);
                        dst[(4 * jj + 2) * 64] = pack2(f.z, f.z);
                        dst[(4 * jj + 3) * 64] = pack2(f.w, f.w);
                    }
                } else {
#pragma unroll
                    for (int jj = 0; jj < 16; jj++) dst[jj * 64] = 0ull;
                }
            }
            {   // h_rnn -> [k][b]
                const float4* hsrc = (const float4*)(g_hrnn + (size_t)fb * HID + k0 + fkq * 8);
                float* hd = &sm.l.h[fkq * 8][fb];
#pragma unroll
                for (int jj = 0; jj < 2; jj++) {
                    float4 f = hsrc[jj];
                    hd[(4 * jj + 0) * 64] = f.x; hd[(4 * jj + 1) * 64] = f.y;
                    hd[(4 * jj + 2) * 64] = f.z; hd[(4 * jj + 3) * 64] = f.w;
                }
            }
            __syncthreads();
#pragma unroll 8
            for (int k = 0; k < KT; k++) {
                ulonglong2 e2 = *(const ulonglong2*)&sm.l.e[vhalf][k][2 * lane];
                ulonglong2 hA = *(const ulonglong2*)&sm.l.h[k][bb];       // broadcast
                ulonglong2 hB = *(const ulonglong2*)&sm.l.h[k][bb + 4];
                ulonglong2 hC = *(const ulonglong2*)&sm.l.h[k][bb + 8];
                ulonglong2 hD = *(const ulonglong2*)&sm.l.h[k][bb + 12];
                acc0[0] = fma2(e2.x, hA.x, acc0[0]); acc1[0] = fma2(e2.y, hA.x, acc1[0]);
                acc0[1] = fma2(e2.x, hA.y, acc0[1]); acc1[1] = fma2(e2.y, hA.y, acc1[1]);
                acc0[2] = fma2(e2.x, hB.x, acc0[2]); acc1[2] = fma2(e2.y, hB.x, acc1[2]);
                acc0[3] = fma2(e2.x, hB.y, acc0[3]); acc1[3] = fma2(e2.y, hB.y, acc1[3]);
                acc0[4] = fma2(e2.x, hC.x, acc0[4]); acc1[4] = fma2(e2.y, hC.x, acc1[4]);
                acc0[5] = fma2(e2.x, hC.y, acc0[5]); acc1[5] = fma2(e2.y, hC.y, acc1[5]);
                acc0[6] = fma2(e2.x, hD.x, acc0[6]); acc1[6] = fma2(e2.y, hD.x, acc1[6]);
                acc0[7] = fma2(e2.x, hD.y, acc0[7]); acc1[7] = fma2(e2.y, hD.y, acc1[7]);
            }
            __syncthreads();
        }

        // epilogue: store logits + per-batch argmax candidates (v ascending)
        float cv[16]; int ci[16];
#pragma unroll
        for (int j = 0; j < 8; j++) {
            float a0x, a0y, a1x, a1y;
            unpack2(acc0[j], a0x, a0y);   // v0   logits for batches bb+2j, bb+2j+1
            unpack2(acc1[j], a1x, a1y);   // v0+1 logits
            if (gval) {
                *(float2*)&out_step[(size_t)(bb + 2 * j)     * VOCAB + v0] = make_float2(a0x, a1x);
                *(float2*)&out_step[(size_t)(bb + 2 * j + 1) * VOCAB + v0] = make_float2(a0y, a1y);
            }
            float bv = NEG_INF; int bx = 0x7fffffff;
            if (gval) {
                bv = a0x; bx = v0;
                if (a1x > bv) { bv = a1x; bx = v0 + 1; }
            }
            cv[2 * j] = bv; ci[2 * j] = bx;
            bv = NEG_INF; bx = 0x7fffffff;
            if (gval) {
                bv = a0y; bx = v0;
                if (a1y > bv) { bv = a1y; bx = v0 + 1; }
            }
            cv[2 * j + 1] = bv; ci[2 * j + 1] = bx;
        }
        // butterfly over all 32 lanes (covering this warp's 64 vocab rows)
#pragma unroll
        for (int j = 0; j < 16; j++) {
            float v = cv[j]; int ix = ci[j];
#pragma unroll
            for (int off = 16; off > 0; off >>= 1) {
                float ov = __shfl_xor_sync(0xffffffffu, v, off);
                int   oi = __shfl_xor_sync(0xffffffffu, ix, off);
                if (ov > v || (ov == v && oi < ix)) { v = ov; ix = oi; }
            }
            cv[j] = v; ci[j] = ix;
        }
        if (lane == 0) {
            const int base = (bid * 2 + vhalf) * BATCH + bb;
#pragma unroll
            for (int j = 0; j < 16; j++) {
                g_pmax[base + j] = cv[j];
                g_pidx[base + j] = ci[j];
            }
        }
    } else {
        // ================= attention block (h or c) ===========================
        const int a     = bid - NLOG;
        const int bi    = a & 63;
        const int which = a >> 6;
        const float* vr = (which ? g_crnn : g_hrnn) + (size_t)bi * HID;
        for (int d = tid; d < HID; d += 256) sm.a.vv[d] = vr[d];
        __syncthreads();
        for (int s = warp; s < SRC; s += 8) {
            float acc = 0.f;
            const float* er = enc + ((size_t)s * BATCH + bi) * HID;
            for (int d = lane; d < HID; d += 32) acc += er[d] * sm.a.vv[d];
#pragma unroll
            for (int o = 16; o > 0; o >>= 1) acc += __shfl_xor_sync(0xffffffffu, acc, o);
            if (lane == 0) sm.a.sc[s] = acc * 0.04419417382415922f; // 1/sqrt(512)
        }
        __syncthreads();
        if (tid == 0) {
            float m = sm.a.sc[0];
            for (int s = 1; s < SRC; s++) m = fmaxf(m, sm.a.sc[s]);
            float sum = 0.f;
            for (int s = 0; s < SRC; s++) { float e = expf(sm.a.sc[s] - m); sm.a.sc[s] = e; sum += e; }
            sm.a.isum = 1.f / sum;
        }
        __syncthreads();
        const float isum = sm.a.isum;
        float* dst = (which ? g_c : g_h) + (size_t)bi * HID;
        for (int d = tid; d < HID; d += 256) {
            float acc = 0.f;
#pragma unroll 10
            for (int s = 0; s < SRC; s++) acc += sm.a.sc[s] * enc[((size_t)s * BATCH + bi) * HID + d];
            dst[d] = acc * isum + sm.a.vv[d];
        }
    }

    // ================= last-block-done final argmax ===========================
    __threadfence();
    __syncthreads();
    if (tid == 0) {
        int old = atomicAdd(&g_done, 1);
        s_last = (old == (int)gridDim.x - 1);
    }
    __syncthreads();
    if (s_last) {
        const int b = tid & 63, grp = tid >> 6;
        float bv = NEG_INF; int bx = 0x7fffffff;
        for (int p = grp; p < 2 * NLOG; p += 4) {
            float v = g_pmax[p * BATCH + b];
            int  ix = g_pidx[p * BATCH + b];
            if (v > bv || (v == bv && ix < bx)) { bv = v; bx = ix; }
        }
        __syncthreads();   // all threads past union reuse of sm before writing sm.m
        sm.m.sv[tid] = bv; sm.m.si[tid] = bx;
        __syncthreads();
        if (tid < 64) {
            for (int g = 1; g < 4; g++) {
                float v = sm.m.sv[tid + 64 * g];
                int  ix = sm.m.si[tid + 64 * g];
                if (v > bv || (v == bv && ix < bx)) { bv = v; bx = ix; }
            }
            g_tok[b] = bx;
            if (write_tok) out_tok[b * STEPS + step] = (float)bx;
        }
        if (tid == 0) g_done = 0;
    }
}

// ---------------- launch: 1 init + 31 x (lstm, fused) -----------------------
extern "C" void kernel_launch(void* const* d_in, const int* in_sizes, int n_in,
                              void* d_out, int out_size) {
    const float* embed   = (const float*)d_in[0];
    const float* fc_bias = (const float*)d_in[1];
    const float* w_ih    = (const float*)d_in[2];
    const float* w_hh    = (const float*)d_in[3];
    const float* b_ih    = (const float*)d_in[4];
    const float* b_hh    = (const float*)d_in[5];
    const float* enc     = (const float*)d_in[6];
    const float* h0      = (const float*)d_in[7];
    const float* c0      = (const float*)d_in[8];
    const int*   t0      = (const int*)d_in[9];
    float* out = (float*)d_out;

    const long long LT = (long long)STEPS * BATCH * VOCAB;  // 99,200,000
    int write_tok = ((long long)out_size >= LT + (long long)BATCH * STEPS) ? 1 : 0;
    float* out_tok = out + LT;

    k_init<<<32, 256>>>(h0, c0, t0);
    for (int t = 0; t < STEPS; t++) {
        k_lstm<<<128, 512>>>(embed, w_ih, w_hh, b_ih, b_hh);
        k_fused<<<NLOG + 128, 256>>>(embed, fc_bias, enc,
                                     out + (long long)t * BATCH * VOCAB,
                                     out_tok, t, write_tok);
    }
}

// round 16
// speedup vs baseline: 1.0599x; 1.0599x over previous
#include <cuda_runtime.h>
#include <math.h>

#define HID   512
#define VOCAB 50000
#define BATCH 64
#define SRC   50
#define STEPS 31
#define VT    128                 /* vocab tile per logits block */
#define NLOG  391                 /* ceil(50000/128) */
#define KT    32                  /* k tile */
#define NTILE (HID / KT)          /* 16 */
#define NEG_INF (-3.402823466e38f)

typedef unsigned long long ull;

// ---------------- persistent device state (no allocations allowed) ----------
__device__ __align__(16) float g_h[BATCH * HID];      // post-attention hidden (carry)
__device__ __align__(16) float g_c[BATCH * HID];      // post-attention cell   (carry)
__device__ __align__(16) float g_hrnn[BATCH * HID];   // raw LSTM outputs this step
__device__ __align__(16) float g_crnn[BATCH * HID];
__device__ int   g_tok[BATCH];
__device__ float g_pmax[NLOG * BATCH];
__device__ int   g_pidx[NLOG * BATCH];
__device__ int   g_done;

// ---------------- f32x2 packed-FMA helpers (Blackwell dual fp32 pipe) -------
__device__ __forceinline__ ull pack2(float x, float y) {
    ull r; asm("mov.b64 %0, {%1,%2};" : "=l"(r) : "f"(x), "f"(y)); return r;
}
__device__ __forceinline__ void unpack2(ull a, float& x, float& y) {
    asm("mov.b64 {%0,%1}, %2;" : "=f"(x), "=f"(y) : "l"(a));
}
__device__ __forceinline__ ull fma2(ull a, ull b, ull c) {
    ull d; asm("fma.rn.f32x2 %0, %1, %2, %3;" : "=l"(d) : "l"(a), "l"(b), "l"(c)); return d;
}
__device__ __forceinline__ float sigmoidf_(float x) { return 1.f / (1.f + expf(-x)); }

// ---------------- init ------------------------------------------------------
__global__ void k_init(const float* __restrict__ h0, const float* __restrict__ c0,
                       const int* __restrict__ t0) {
    int tid = blockIdx.x * blockDim.x + threadIdx.x;
    for (int i = tid; i < BATCH * HID; i += blockDim.x * gridDim.x) {
        g_h[i] = h0[i];
        g_c[i] = c0[i];
    }
    if (tid < BATCH) g_tok[tid] = t0[tid];
    if (tid == 0) g_done = 0;
}

// ---------------- LSTM cell -------------------------------------------------
// grid 128 x 128 threads. Block = 4 hidden dims x 4 gates = 16 gate rows.
// Thread = (row-pair rp, bpair-pair bp2): 2 rows x 2 batch-pairs = 4 accs.
// Per k: 4 LDS.128 feed 8 FFMA2 (register reuse halves crossbar/MAC).
// Per-acc accumulation order: k ascending, wi before wh (bit-identical to R14).
__global__ void __launch_bounds__(128) k_lstm(const float* __restrict__ embed,
                       const float* __restrict__ w_ih,
                       const float* __restrict__ w_hh,
                       const float* __restrict__ b_ih,
                       const float* __restrict__ b_hh) {
    __shared__ ull   wi_t[KT][16];     // [k][row] splatted pairs, 4KB
    __shared__ ull   wh_t[KT][16];     // 4KB
    __shared__ ull   x_p [KT][32];     // [k][bpair] packed (x[2bp],x[2bp+1]), 8KB
    __shared__ ull   h_p [KT][32];     // 8KB
    __shared__ float gate_sm[16][66];
    __shared__ int   tok_sm[BATCH];

    const int tid = threadIdx.x;
    const int hd0 = blockIdx.x * 4;
    if (tid < BATCH) tok_sm[tid] = g_tok[tid];

    // compute roles: rows 2rp, 2rp+1; batch pairs 2bp2, 2bp2+1
    const int rp  = tid & 7;
    const int bp2 = tid >> 3;           // 0..15
    const int row0 = 2 * rp, row1 = 2 * rp + 1;
    const int j0 = (row0 >> 2) * HID + hd0 + (row0 & 3);
    const int j1 = (row1 >> 2) * HID + hd0 + (row1 & 3);
    const float bias0 = b_ih[j0] + b_hh[j0];
    const float bias1 = b_ih[j1] + b_hh[j1];
    ull acc00 = pack2(bias0, bias0), acc01 = pack2(bias0, bias0);
    ull acc10 = pack2(bias1, bias1), acc11 = pack2(bias1, bias1);

    // fill roles
    const int w_r  = tid & 15;          // weight row 0..15
    const int w_kq = tid >> 4;          // 0..7 k-quads of 4
    const int w_j  = (w_r >> 2) * HID + hd0 + (w_r & 3);
    const float* wisrc = w_ih + (size_t)w_j * HID;
    const float* whsrc = w_hh + (size_t)w_j * HID;
    const int f_bp = tid & 31;          // batch pair 0..31
    const int f_kq = tid >> 5;          // 0..3 k-groups of 8
    __syncthreads();                    // tok_sm visible

    const float* xs0 = embed + (size_t)tok_sm[2 * f_bp]     * HID;
    const float* xs1 = embed + (size_t)tok_sm[2 * f_bp + 1] * HID;
    const float* hs0 = g_h + (size_t)(2 * f_bp) * HID;
    const float* hs1 = g_h + (size_t)(2 * f_bp + 1) * HID;

    // prefetch tile 0
    float4 wiq = *(const float4*)(wisrc + 4 * w_kq);
    float4 whq = *(const float4*)(whsrc + 4 * w_kq);
    float4 xa0 = *(const float4*)(xs0 + 8 * f_kq);
    float4 xa1 = *(const float4*)(xs0 + 8 * f_kq + 4);
    float4 xb0 = *(const float4*)(xs1 + 8 * f_kq);
    float4 xb1 = *(const float4*)(xs1 + 8 * f_kq + 4);
    float4 ha0 = *(const float4*)(hs0 + 8 * f_kq);
    float4 ha1 = *(const float4*)(hs0 + 8 * f_kq + 4);
    float4 hb0 = *(const float4*)(hs1 + 8 * f_kq);
    float4 hb1 = *(const float4*)(hs1 + 8 * f_kq + 4);

    for (int kt = 0; kt < NTILE; kt++) {
        __syncthreads();                // previous compute done reading smem
        {   // weights -> splatted [k][row]
            wi_t[4 * w_kq + 0][w_r] = pack2(wiq.x, wiq.x);
            wi_t[4 * w_kq + 1][w_r] = pack2(wiq.y, wiq.y);
            wi_t[4 * w_kq + 2][w_r] = pack2(wiq.z, wiq.z);
            wi_t[4 * w_kq + 3][w_r] = pack2(wiq.w, wiq.w);
            wh_t[4 * w_kq + 0][w_r] = pack2(whq.x, whq.x);
            wh_t[4 * w_kq + 1][w_r] = pack2(whq.y, whq.y);
            wh_t[4 * w_kq + 2][w_r] = pack2(whq.z, whq.z);
            wh_t[4 * w_kq + 3][w_r] = pack2(whq.w, whq.w);
        }
        {   // x/h -> [k][bpair] packed pairs
            const int kk = 8 * f_kq;
            x_p[kk + 0][f_bp] = pack2(xa0.x, xb0.x);
            x_p[kk + 1][f_bp] = pack2(xa0.y, xb0.y);
            x_p[kk + 2][f_bp] = pack2(xa0.z, xb0.z);
            x_p[kk + 3][f_bp] = pack2(xa0.w, xb0.w);
            x_p[kk + 4][f_bp] = pack2(xa1.x, xb1.x);
            x_p[kk + 5][f_bp] = pack2(xa1.y, xb1.y);
            x_p[kk + 6][f_bp] = pack2(xa1.z, xb1.z);
            x_p[kk + 7][f_bp] = pack2(xa1.w, xb1.w);
            h_p[kk + 0][f_bp] = pack2(ha0.x, hb0.x);
            h_p[kk + 1][f_bp] = pack2(ha0.y, hb0.y);
            h_p[kk + 2][f_bp] = pack2(ha0.z, hb0.z);
            h_p[kk + 3][f_bp] = pack2(ha0.w, hb0.w);
            h_p[kk + 4][f_bp] = pack2(ha1.x, hb1.x);
            h_p[kk + 5][f_bp] = pack2(ha1.y, hb1.y);
            h_p[kk + 6][f_bp] = pack2(ha1.z, hb1.z);
            h_p[kk + 7][f_bp] = pack2(ha1.w, hb1.w);
        }
        __syncthreads();
        if (kt + 1 < NTILE) {           // prefetch next tile (overlaps compute)
            const int k0n = (kt + 1) * KT;
            wiq = *(const float4*)(wisrc + k0n + 4 * w_kq);
            whq = *(const float4*)(whsrc + k0n + 4 * w_kq);
            xa0 = *(const float4*)(xs0 + k0n + 8 * f_kq);
            xa1 = *(const float4*)(xs0 + k0n + 8 * f_kq + 4);
            xb0 = *(const float4*)(xs1 + k0n + 8 * f_kq);
            xb1 = *(const float4*)(xs1 + k0n + 8 * f_kq + 4);
            ha0 = *(const float4*)(hs0 + k0n + 8 * f_kq);
            ha1 = *(const float4*)(hs0 + k0n + 8 * f_kq + 4);
            hb0 = *(const float4*)(hs1 + k0n + 8 * f_kq);
            hb1 = *(const float4*)(hs1 + k0n + 8 * f_kq + 4);
        }
#pragma unroll 8
        for (int k = 0; k < KT; k++) {
            ulonglong2 wi2 = *(const ulonglong2*)&wi_t[k][2 * rp];   // rows 2rp,2rp+1
            ulonglong2 wh2 = *(const ulonglong2*)&wh_t[k][2 * rp];
            ulonglong2 xv2 = *(const ulonglong2*)&x_p[k][2 * bp2];   // bpairs 2bp2,2bp2+1
            ulonglong2 hv2 = *(const ulonglong2*)&h_p[k][2 * bp2];
            acc00 = fma2(wi2.x, xv2.x, acc00);
            acc00 = fma2(wh2.x, hv2.x, acc00);
            acc01 = fma2(wi2.x, xv2.y, acc01);
            acc01 = fma2(wh2.x, hv2.y, acc01);
            acc10 = fma2(wi2.y, xv2.x, acc10);
            acc10 = fma2(wh2.y, hv2.x, acc10);
            acc11 = fma2(wi2.y, xv2.y, acc11);
            acc11 = fma2(wh2.y, hv2.y, acc11);
        }
    }
    *(ull*)&gate_sm[row0][4 * bp2]     = acc00;
    *(ull*)&gate_sm[row0][4 * bp2 + 2] = acc01;
    *(ull*)&gate_sm[row1][4 * bp2]     = acc10;
    *(ull*)&gate_sm[row1][4 * bp2 + 2] = acc11;
    __syncthreads();
    // cell update: 4 hidden dims x 64 batches (gate order i,f,g,o)
    for (int i = tid; i < 256; i += 128) {
        int dd = i >> 6, b = i & 63;
        float ig = sigmoidf_(gate_sm[dd][b]);
        float fg = sigmoidf_(gate_sm[4 + dd][b]);
        float gg = tanhf(gate_sm[8 + dd][b]);
        float og = sigmoidf_(gate_sm[12 + dd][b]);
        int idx = b * HID + hd0 + dd;
        float cn = fg * g_c[idx] + ig * gg;
        g_crnn[idx] = cn;
        g_hrnn[idx] = og * tanhf(cn);
    }
}

// ---------------- fused: logits(+argmax partials) | attention | final argmax
// (exact R14 version — known 5461us total; do not touch the inner loop)
struct SmLogits { ull e[2][KT][64]; float h[KT][64]; };    // 32KB + 8KB
struct SmAttn   { float vv[HID]; float sc[64]; float isum; };
struct SmAmax   { float sv[256]; int si[256]; };
union SmU { SmLogits l; SmAttn a; SmAmax m; };

__global__ void __launch_bounds__(256) k_fused(
        const float* __restrict__ embed, const float* __restrict__ fc_bias,
        const float* __restrict__ enc, float* __restrict__ out_step,
        float* __restrict__ out_tok, int step, int write_tok) {
    __shared__ SmU sm;
    __shared__ int s_last;

    const int tid  = threadIdx.x;
    const int lane = tid & 31;
    const int warp = tid >> 5;
    const int bid  = blockIdx.x;

    if (bid < NLOG) {
        // ================= logits block: 128 vocab x 64 batch =================
        const int vbase = bid * VT;
        const int vL = vbase + 2 * lane;        // iv 0,1
        const int vH = vbase + 64 + 2 * lane;   // iv 2,3

        float bz0 = (vL     < VOCAB) ? fc_bias[vL]     : 0.f;
        float bz1 = (vL + 1 < VOCAB) ? fc_bias[vL + 1] : 0.f;
        float bz2 = (vH     < VOCAB) ? fc_bias[vH]     : 0.f;
        float bz3 = (vH + 1 < VOCAB) ? fc_bias[vH + 1] : 0.f;
        ull acc[4][4];
#pragma unroll
        for (int bp = 0; bp < 4; bp++) {
            acc[0][bp] = pack2(bz0, bz0); acc[1][bp] = pack2(bz1, bz1);
            acc[2][bp] = pack2(bz2, bz2); acc[3][bp] = pack2(bz3, bz3);
        }

        const int fv  = tid & 127;   // fill vocab row
        const int fkh = tid >> 7;    // 0/1: which 16-k half
        const int fb  = tid & 63;    // fill batch
        const int fkq = tid >> 6;    // 0..3: 8-k group

        for (int k0 = 0; k0 < HID; k0 += KT) {
            {   // embed -> dup'd [half][k][v]
                const int gv = vbase + fv;
                ull* dst = &sm.l.e[fv >> 6][fkh * 16][fv & 63];
                if (gv < VOCAB) {
                    const float4* src = (const float4*)(embed + (size_t)gv * HID + k0 + fkh * 16);
#pragma unroll
                    for (int jj = 0; jj < 4; jj++) {
                        float4 f = src[jj];
                        dst[(4 * jj + 0) * 64] = pack2(f.x, f.x);
                        dst[(4 * jj + 1) * 64] = pack2(f.y, f.y);
                        dst[(4 * jj + 2) * 64] = pack2(f.z, f.z);
                        dst[(4 * jj + 3) * 64] = pack2(f.w, f.w);
                    }
                } else {
#pragma unroll
                    for (int jj = 0; jj < 16; jj++) dst[jj * 64] = 0ull;
                }
            }
            {   // h_rnn -> [k][b]
                const float4* hsrc = (const float4*)(g_hrnn + (size_t)fb * HID + k0 + fkq * 8);
                float* hd = &sm.l.h[fkq * 8][fb];
#pragma unroll
                for (int jj = 0; jj < 2; jj++) {
                    float4 f = hsrc[jj];
                    hd[(4 * jj + 0) * 64] = f.x; hd[(4 * jj + 1) * 64] = f.y;
                    hd[(4 * jj + 2) * 64] = f.z; hd[(4 * jj + 3) * 64] = f.w;
                }
            }
            __syncthreads();
#pragma unroll 8
            for (int k = 0; k < KT; k++) {
                ulonglong2 eL = *(const ulonglong2*)&sm.l.e[0][k][2 * lane];
                ulonglong2 eH = *(const ulonglong2*)&sm.l.e[1][k][2 * lane];
                ulonglong2 hA = *(const ulonglong2*)&sm.l.h[k][8 * warp];
                ulonglong2 hB = *(const ulonglong2*)&sm.l.h[k][8 * warp + 4];
                acc[0][0] = fma2(eL.x, hA.x, acc[0][0]); acc[0][1] = fma2(eL.x, hA.y, acc[0][1]);
                acc[0][2] = fma2(eL.x, hB.x, acc[0][2]); acc[0][3] = fma2(eL.x, hB.y, acc[0][3]);
                acc[1][0] = fma2(eL.y, hA.x, acc[1][0]); acc[1][1] = fma2(eL.y, hA.y, acc[1][1]);
                acc[1][2] = fma2(eL.y, hB.x, acc[1][2]); acc[1][3] = fma2(eL.y, hB.y, acc[1][3]);
                acc[2][0] = fma2(eH.x, hA.x, acc[2][0]); acc[2][1] = fma2(eH.x, hA.y, acc[2][1]);
                acc[2][2] = fma2(eH.x, hB.x, acc[2][2]); acc[2][3] = fma2(eH.x, hB.y, acc[2][3]);
                acc[3][0] = fma2(eH.y, hA.x, acc[3][0]); acc[3][1] = fma2(eH.y, hA.y, acc[3][1]);
                acc[3][2] = fma2(eH.y, hB.x, acc[3][2]); acc[3][3] = fma2(eH.y, hB.y, acc[3][3]);
            }
            __syncthreads();
        }

        // epilogue: store logits + per-batch argmax candidates (v ascending)
        float pv[8]; int pi[8];
#pragma unroll
        for (int bp = 0; bp < 4; bp++) {
            float l0e, l0o, l1e, l1o, l2e, l2o, l3e, l3o;
            unpack2(acc[0][bp], l0e, l0o);
            unpack2(acc[1][bp], l1e, l1o);
            unpack2(acc[2][bp], l2e, l2o);
            unpack2(acc[3][bp], l3e, l3o);
            const int be = 8 * warp + 2 * bp, bo = be + 1;
            if (vL < VOCAB) {
                *(float2*)&out_step[(size_t)be * VOCAB + vL] = make_float2(l0e, l1e);
                *(float2*)&out_step[(size_t)bo * VOCAB + vL] = make_float2(l0o, l1o);
            }
            if (vH < VOCAB) {
                *(float2*)&out_step[(size_t)be * VOCAB + vH] = make_float2(l2e, l3e);
                *(float2*)&out_step[(size_t)bo * VOCAB + vH] = make_float2(l2o, l3o);
            }
            float bv = NEG_INF; int bx = 0x7fffffff;
            if (vL < VOCAB) {
                if (l0e > bv) { bv = l0e; bx = vL; }
                if (l1e > bv) { bv = l1e; bx = vL + 1; }
            }
            if (vH < VOCAB) {
                if (l2e > bv) { bv = l2e; bx = vH; }
                if (l3e > bv) { bv = l3e; bx = vH + 1; }
            }
            pv[2 * bp] = bv; pi[2 * bp] = bx;
            bv = NEG_INF; bx = 0x7fffffff;
            if (vL < VOCAB) {
                if (l0o > bv) { bv = l0o; bx = vL; }
                if (l1o > bv) { bv = l1o; bx = vL + 1; }
            }
            if (vH < VOCAB) {
                if (l2o > bv) { bv = l2o; bx = vH; }
                if (l3o > bv) { bv = l3o; bx = vH + 1; }
            }
            pv[2 * bp + 1] = bv; pi[2 * bp + 1] = bx;
        }
#pragma unroll
        for (int s = 0; s < 8; s++) {
            float v = pv[s]; int ix = pi[s];
#pragma unroll
            for (int off = 16; off > 0; off >>= 1) {
                float ov = __shfl_xor_sync(0xffffffffu, v, off);
                int   oi = __shfl_xor_sync(0xffffffffu, ix, off);
                if (ov > v || (ov == v && oi < ix)) { v = ov; ix = oi; }
            }
            if (lane == 0) {
                g_pmax[bid * 64 + 8 * warp + s] = v;
                g_pidx[bid * 64 + 8 * warp + s] = ix;
            }
        }
    } else {
        // ================= attention block (h or c) ===========================
        const int a     = bid - NLOG;
        const int bi    = a & 63;
        const int which = a >> 6;
        const float* vr = (which ? g_crnn : g_hrnn) + (size_t)bi * HID;
        for (int d = tid; d < HID; d += 256) sm.a.vv[d] = vr[d];
        __syncthreads();
        for (int s = warp; s < SRC; s += 8) {
            float acc = 0.f;
            const float* er = enc + ((size_t)s * BATCH + bi) * HID;
            for (int d = lane; d < HID; d += 32) acc += er[d] * sm.a.vv[d];
#pragma unroll
            for (int o = 16; o > 0; o >>= 1) acc += __shfl_xor_sync(0xffffffffu, acc, o);
            if (lane == 0) sm.a.sc[s] = acc * 0.04419417382415922f; // 1/sqrt(512)
        }
        __syncthreads();
        if (tid == 0) {
            float m = sm.a.sc[0];
            for (int s = 1; s < SRC; s++) m = fmaxf(m, sm.a.sc[s]);
            float sum = 0.f;
            for (int s = 0; s < SRC; s++) { float e = expf(sm.a.sc[s] - m); sm.a.sc[s] = e; sum += e; }
            sm.a.isum = 1.f / sum;
        }
        __syncthreads();
        const float isum = sm.a.isum;
        float* dst = (which ? g_c : g_h) + (size_t)bi * HID;
        for (int d = tid; d < HID; d += 256) {
            float acc = 0.f;
#pragma unroll 10
            for (int s = 0; s < SRC; s++) acc += sm.a.sc[s] * enc[((size_t)s * BATCH + bi) * HID + d];
            dst[d] = acc * isum + sm.a.vv[d];
        }
    }

    // ================= last-block-done final argmax ===========================
    __threadfence();
    __syncthreads();
    if (tid == 0) {
        int old = atomicAdd(&g_done, 1);
        s_last = (old == (int)gridDim.x - 1);
    }
    __syncthreads();
    if (s_last) {
        const int b = tid & 63, grp = tid >> 6;
        float bv = NEG_INF; int bx = 0x7fffffff;
        for (int p = grp; p < NLOG; p += 4) {
            float v = g_pmax[p * 64 + b];
            int  ix = g_pidx[p * 64 + b];
            if (v > bv || (v == bv && ix < bx)) { bv = v; bx = ix; }
        }
        __syncthreads();   // all threads past union reuse of sm before writing sm.m
        sm.m.sv[tid] = bv; sm.m.si[tid] = bx;
        __syncthreads();
        if (tid < 64) {
            for (int g = 1; g < 4; g++) {
                float v = sm.m.sv[tid + 64 * g];
                int  ix = sm.m.si[tid + 64 * g];
                if (v > bv || (v == bv && ix < bx)) { bv = v; bx = ix; }
            }
            g_tok[b] = bx;
            if (write_tok) out_tok[b * STEPS + step] = (float)bx;
        }
        if (tid == 0) g_done = 0;
    }
}

// ---------------- launch: 1 init + 31 x (lstm, fused) -----------------------
extern "C" void kernel_launch(void* const* d_in, const int* in_sizes, int n_in,
                              void* d_out, int out_size) {
    const float* embed   = (const float*)d_in[0];
    const float* fc_bias = (const float*)d_in[1];
    const float* w_ih    = (const float*)d_in[2];
    const float* w_hh    = (const float*)d_in[3];
    const float* b_ih    = (const float*)d_in[4];
    const float* b_hh    = (const float*)d_in[5];
    const float* enc     = (const float*)d_in[6];
    const float* h0      = (const float*)d_in[7];
    const float* c0      = (const float*)d_in[8];
    const int*   t0      = (const int*)d_in[9];
    float* out = (float*)d_out;

    const long long LT = (long long)STEPS * BATCH * VOCAB;  // 99,200,000
    int write_tok = ((long long)out_size >= LT + (long long)BATCH * STEPS) ? 1 : 0;
    float* out_tok = out + LT;

    k_init<<<32, 256>>>(h0, c0, t0);
    for (int t = 0; t < STEPS; t++) {
        k_lstm<<<128, 128>>>(embed, w_ih, w_hh, b_ih, b_hh);
        k_fused<<<NLOG + 128, 256>>>(embed, fc_bias, enc,
                                     out + (long long)t * BATCH * VOCAB,
                                     out_tok, t, write_tok);
    }
}

// round 17
// speedup vs baseline: 1.6967x; 1.6008x over previous
#include <cuda_runtime.h>
#include <math.h>

#define HID   512
#define VOCAB 50000
#define BATCH 64
#define SRC   50
#define STEPS 31
#define VT    128                 /* vocab tile per logits block */
#define NLOG  391                 /* ceil(50000/128) */
#define KT    32                  /* k tile */
#define NTILE (HID / KT)          /* 16 */
#define NEG_INF (-3.402823466e38f)

typedef unsigned long long ull;

// ---------------- persistent device state (no allocations allowed) ----------
__device__ __align__(16) float g_h[BATCH * HID];      // post-attention hidden (carry)
__device__ __align__(16) float g_c[BATCH * HID];      // post-attention cell   (carry)
__device__ __align__(16) float g_hrnn[BATCH * HID];   // raw LSTM outputs this step
__device__ __align__(16) float g_crnn[BATCH * HID];
__device__ int   g_tok[BATCH];
__device__ float g_pmax[NLOG * BATCH];
__device__ int   g_pidx[NLOG * BATCH];
__device__ int   g_done;

// ---------------- f32x2 packed-FMA helpers (Blackwell dual fp32 pipe) -------
__device__ __forceinline__ ull pack2(float x, float y) {
    ull r; asm("mov.b64 %0, {%1,%2};" : "=l"(r) : "f"(x), "f"(y)); return r;
}
__device__ __forceinline__ void unpack2(ull a, float& x, float& y) {
    asm("mov.b64 {%0,%1}, %2;" : "=f"(x), "=f"(y) : "l"(a));
}
__device__ __forceinline__ ull fma2(ull a, ull b, ull c) {
    ull d; asm("fma.rn.f32x2 %0, %1, %2, %3;" : "=l"(d) : "l"(a), "l"(b), "l"(c)); return d;
}
__device__ __forceinline__ float sigmoidf_(float x) { return 1.f / (1.f + expf(-x)); }

// ---------------- init ------------------------------------------------------
__global__ void k_init(const float* __restrict__ h0, const float* __restrict__ c0,
                       const int* __restrict__ t0) {
    int tid = blockIdx.x * blockDim.x + threadIdx.x;
    for (int i = tid; i < BATCH * HID; i += blockDim.x * gridDim.x) {
        g_h[i] = h0[i];
        g_c[i] = c0[i];
    }
    if (tid < BATCH) g_tok[tid] = t0[tid];
    if (tid == 0) g_done = 0;
}

// ---------------- LSTM cell (exact R14 version, measured 37.3us) ------------
__global__ void __launch_bounds__(512) k_lstm(const float* __restrict__ embed,
                       const float* __restrict__ w_ih,
                       const float* __restrict__ w_hh,
                       const float* __restrict__ b_ih,
                       const float* __restrict__ b_hh) {
    __shared__ ull   wi_t[16][KT + 2];   // [row][k] splatted pairs, stride 34 ull
    __shared__ ull   wh_t[16][KT + 2];
    __shared__ ull   x_p [32][KT + 2];   // [bpair][k] (x[2bp][k], x[2bp+1][k])
    __shared__ ull   h_p [32][KT + 2];
    __shared__ float gate_sm[16][66];
    __shared__ int   tok_sm[BATCH];

    const int tid = threadIdx.x;
    const int hd0 = blockIdx.x * 4;
    if (tid < BATCH) tok_sm[tid] = g_tok[tid];

    const int rr = tid & 15;            // gate row: g*4 + dloc
    const int bq = tid >> 4;            // 0..31 batch pair
    const int jrow = (rr >> 2) * HID + hd0 + (rr & 3);
    const float bias = b_ih[jrow] + b_hh[jrow];
    ull acc = pack2(bias, bias);

    const int w_kp = tid & 15;          // 16 k-pairs (coalesced along k)
    const int w_rr = (tid >> 4) & 15;
    const int w_m  = tid >> 8;
    const int w_j  = (w_rr >> 2) * HID + hd0 + (w_rr & 3);
    const float* wsrc = (w_m ? w_hh : w_ih) + (size_t)w_j * HID;
    const int f_bp = tid & 31;          // batch pair
    const int f_kq = (tid >> 5) & 7;    // 8 groups of 4 k
    __syncthreads();                    // tok_sm visible

    const float *s0, *s1;
    if (w_m) { s0 = g_h + (size_t)(2 * f_bp) * HID;
               s1 = g_h + (size_t)(2 * f_bp + 1) * HID; }
    else     { s0 = embed + (size_t)tok_sm[2 * f_bp]     * HID;
               s1 = embed + (size_t)tok_sm[2 * f_bp + 1] * HID; }

    float2 wp = *(const float2*)(wsrc + 2 * w_kp);
    float4 pa = *(const float4*)(s0 + 4 * f_kq);
    float4 pb = *(const float4*)(s1 + 4 * f_kq);

    for (int kt = 0; kt < NTILE; kt++) {
        __syncthreads();
        {
            ull* wt = (w_m ? &wh_t[0][0] : &wi_t[0][0]) + w_rr * (KT + 2);
            ulonglong2 wv; wv.x = pack2(wp.x, wp.x); wv.y = pack2(wp.y, wp.y);
            *(ulonglong2*)&wt[2 * w_kp] = wv;
        }
        {
            ull* xt = (w_m ? &h_p[0][0] : &x_p[0][0]) + f_bp * (KT + 2);
            ulonglong2 v0; v0.x = pack2(pa.x, pb.x); v0.y = pack2(pa.y, pb.y);
            ulonglong2 v1; v1.x = pack2(pa.z, pb.z); v1.y = pack2(pa.w, pb.w);
            *(ulonglong2*)&xt[4 * f_kq]     = v0;
            *(ulonglong2*)&xt[4 * f_kq + 2] = v1;
        }
        __syncthreads();
        if (kt + 1 < NTILE) {
            const int k0n = (kt + 1) * KT;
            wp = *(const float2*)(wsrc + k0n + 2 * w_kp);
            pa = *(const float4*)(s0 + k0n + 4 * f_kq);
            pb = *(const float4*)(s1 + k0n + 4 * f_kq);
        }
#pragma unroll
        for (int k = 0; k < KT; k += 2) {
            ulonglong2 wi2 = *(const ulonglong2*)&wi_t[rr][k];
            ulonglong2 wh2 = *(const ulonglong2*)&wh_t[rr][k];
            ulonglong2 xv2 = *(const ulonglong2*)&x_p[bq][k];
            ulonglong2 hv2 = *(const ulonglong2*)&h_p[bq][k];
            acc = fma2(wi2.x, xv2.x, acc);
            acc = fma2(wh2.x, hv2.x, acc);
            acc = fma2(wi2.y, xv2.y, acc);
            acc = fma2(wh2.y, hv2.y, acc);
        }
    }
    *(ull*)&gate_sm[rr][2 * bq] = acc;
    __syncthreads();
    if (tid < 256) {
        int dd = tid >> 6, b = tid & 63;
        float ig = sigmoidf_(gate_sm[dd][b]);
        float fg = sigmoidf_(gate_sm[4 + dd][b]);
        float gg = tanhf(gate_sm[8 + dd][b]);
        float og = sigmoidf_(gate_sm[12 + dd][b]);
        int idx = b * HID + hd0 + dd;
        float cn = fg * g_c[idx] + ig * gg;
        g_crnn[idx] = cn;
        g_hrnn[idx] = og * tanhf(cn);
    }
}

// ---------------- fused: logits(+argmax partials) | attention | final argmax
// (exact R14 version — measured best; do not touch)
struct SmLogits { ull e[2][KT][64]; float h[KT][64]; };    // 32KB + 8KB
struct SmAttn   { float vv[HID]; float sc[64]; float isum; };
struct SmAmax   { float sv[256]; int si[256]; };
union SmU { SmLogits l; SmAttn a; SmAmax m; };

__global__ void __launch_bounds__(256) k_fused(
        const float* __restrict__ embed, const float* __restrict__ fc_bias,
        const float* __restrict__ enc, float* __restrict__ out_step,
        float* __restrict__ out_tok, int step, int write_tok) {
    __shared__ SmU sm;
    __shared__ int s_last;

    const int tid  = threadIdx.x;
    const int lane = tid & 31;
    const int warp = tid >> 5;
    const int bid  = blockIdx.x;

    if (bid < NLOG) {
        // ================= logits block: 128 vocab x 64 batch =================
        const int vbase = bid * VT;
        const int vL = vbase + 2 * lane;        // iv 0,1
        const int vH = vbase + 64 + 2 * lane;   // iv 2,3

        float bz0 = (vL     < VOCAB) ? fc_bias[vL]     : 0.f;
        float bz1 = (vL + 1 < VOCAB) ? fc_bias[vL + 1] : 0.f;
        float bz2 = (vH     < VOCAB) ? fc_bias[vH]     : 0.f;
        float bz3 = (vH + 1 < VOCAB) ? fc_bias[vH + 1] : 0.f;
        ull acc[4][4];
#pragma unroll
        for (int bp = 0; bp < 4; bp++) {
            acc[0][bp] = pack2(bz0, bz0); acc[1][bp] = pack2(bz1, bz1);
            acc[2][bp] = pack2(bz2, bz2); acc[3][bp] = pack2(bz3, bz3);
        }

        const int fv  = tid & 127;   // fill vocab row
        const int fkh = tid >> 7;    // 0/1: which 16-k half
        const int fb  = tid & 63;    // fill batch
        const int fkq = tid >> 6;    // 0..3: 8-k group

        for (int k0 = 0; k0 < HID; k0 += KT) {
            {   // embed -> dup'd [half][k][v]
                const int gv = vbase + fv;
                ull* dst = &sm.l.e[fv >> 6][fkh * 16][fv & 63];
                if (gv < VOCAB) {
                    const float4* src = (const float4*)(embed + (size_t)gv * HID + k0 + fkh * 16);
#pragma unroll
                    for (int jj = 0; jj < 4; jj++) {
                        float4 f = src[jj];
                        dst[(4 * jj + 0) * 64] = pack2(f.x, f.x);
                        dst[(4 * jj + 1) * 64] = pack2(f.y, f.y);
                        dst[(4 * jj + 2) * 64] = pack2(f.z, f.z);
                        dst[(4 * jj + 3) * 64] = pack2(f.w, f.w);
                    }
                } else {
#pragma unroll
                    for (int jj = 0; jj < 16; jj++) dst[jj * 64] = 0ull;
                }
            }
            {   // h_rnn -> [k][b]
                const float4* hsrc = (const float4*)(g_hrnn + (size_t)fb * HID + k0 + fkq * 8);
                float* hd = &sm.l.h[fkq * 8][fb];
#pragma unroll
                for (int jj = 0; jj < 2; jj++) {
                    float4 f = hsrc[jj];
                    hd[(4 * jj + 0) * 64] = f.x; hd[(4 * jj + 1) * 64] = f.y;
                    hd[(4 * jj + 2) * 64] = f.z; hd[(4 * jj + 3) * 64] = f.w;
                }
            }
            __syncthreads();
#pragma unroll 8
            for (int k = 0; k < KT; k++) {
                ulonglong2 eL = *(const ulonglong2*)&sm.l.e[0][k][2 * lane];
                ulonglong2 eH = *(const ulonglong2*)&sm.l.e[1][k][2 * lane];
                ulonglong2 hA = *(const ulonglong2*)&sm.l.h[k][8 * warp];
                ulonglong2 hB = *(const ulonglong2*)&sm.l.h[k][8 * warp + 4];
                acc[0][0] = fma2(eL.x, hA.x, acc[0][0]); acc[0][1] = fma2(eL.x, hA.y, acc[0][1]);
                acc[0][2] = fma2(eL.x, hB.x, acc[0][2]); acc[0][3] = fma2(eL.x, hB.y, acc[0][3]);
                acc[1][0] = fma2(eL.y, hA.x, acc[1][0]); acc[1][1] = fma2(eL.y, hA.y, acc[1][1]);
                acc[1][2] = fma2(eL.y, hB.x, acc[1][2]); acc[1][3] = fma2(eL.y, hB.y, acc[1][3]);
                acc[2][0] = fma2(eH.x, hA.x, acc[2][0]); acc[2][1] = fma2(eH.x, hA.y, acc[2][1]);
                acc[2][2] = fma2(eH.x, hB.x, acc[2][2]); acc[2][3] = fma2(eH.x, hB.y, acc[2][3]);
                acc[3][0] = fma2(eH.y, hA.x, acc[3][0]); acc[3][1] = fma2(eH.y, hA.y, acc[3][1]);
                acc[3][2] = fma2(eH.y, hB.x, acc[3][2]); acc[3][3] = fma2(eH.y, hB.y, acc[3][3]);
            }
            __syncthreads();
        }

        // epilogue: store logits + per-batch argmax candidates (v ascending)
        float pv[8]; int pi[8];
#pragma unroll
        for (int bp = 0; bp < 4; bp++) {
            float l0e, l0o, l1e, l1o, l2e, l2o, l3e, l3o;
            unpack2(acc[0][bp], l0e, l0o);
            unpack2(acc[1][bp], l1e, l1o);
            unpack2(acc[2][bp], l2e, l2o);
            unpack2(acc[3][bp], l3e, l3o);
            const int be = 8 * warp + 2 * bp, bo = be + 1;
            if (vL < VOCAB) {
                *(float2*)&out_step[(size_t)be * VOCAB + vL] = make_float2(l0e, l1e);
                *(float2*)&out_step[(size_t)bo * VOCAB + vL] = make_float2(l0o, l1o);
            }
            if (vH < VOCAB) {
                *(float2*)&out_step[(size_t)be * VOCAB + vH] = make_float2(l2e, l3e);
                *(float2*)&out_step[(size_t)bo * VOCAB + vH] = make_float2(l2o, l3o);
            }
            float bv = NEG_INF; int bx = 0x7fffffff;
            if (vL < VOCAB) {
                if (l0e > bv) { bv = l0e; bx = vL; }
                if (l1e > bv) { bv = l1e; bx = vL + 1; }
            }
            if (vH < VOCAB) {
                if (l2e > bv) { bv = l2e; bx = vH; }
                if (l3e > bv) { bv = l3e; bx = vH + 1; }
            }
            pv[2 * bp] = bv; pi[2 * bp] = bx;
            bv = NEG_INF; bx = 0x7fffffff;
            if (vL < VOCAB) {
                if (l0o > bv) { bv = l0o; bx = vL; }
                if (l1o > bv) { bv = l1o; bx = vL + 1; }
            }
            if (vH < VOCAB) {
                if (l2o > bv) { bv = l2o; bx = vH; }
                if (l3o > bv) { bv = l3o; bx = vH + 1; }
            }
            pv[2 * bp + 1] = bv; pi[2 * bp + 1] = bx;
        }
#pragma unroll
        for (int s = 0; s < 8; s++) {
            float v = pv[s]; int ix = pi[s];
#pragma unroll
            for (int off = 16; off > 0; off >>= 1) {
                float ov = __shfl_xor_sync(0xffffffffu, v, off);
                int   oi = __shfl_xor_sync(0xffffffffu, ix, off);
                if (ov > v || (ov == v && oi < ix)) { v = ov; ix = oi; }
            }
            if (lane == 0) {
                g_pmax[bid * 64 + 8 * warp + s] = v;
                g_pidx[bid * 64 + 8 * warp + s] = ix;
            }
        }
    } else {
        // ================= attention block (h or c) ===========================
        const int a     = bid - NLOG;
        const int bi    = a & 63;
        const int which = a >> 6;
        const float* vr = (which ? g_crnn : g_hrnn) + (size_t)bi * HID;
        for (int d = tid; d < HID; d += 256) sm.a.vv[d] = vr[d];
        __syncthreads();
        for (int s = warp; s < SRC; s += 8) {
            float acc = 0.f;
            const float* er = enc + ((size_t)s * BATCH + bi) * HID;
            for (int d = lane; d < HID; d += 32) acc += er[d] * sm.a.vv[d];
#pragma unroll
            for (int o = 16; o > 0; o >>= 1) acc += __shfl_xor_sync(0xffffffffu, acc, o);
            if (lane == 0) sm.a.sc[s] = acc * 0.04419417382415922f; // 1/sqrt(512)
        }
        __syncthreads();
        if (tid == 0) {
            float m = sm.a.sc[0];
            for (int s = 1; s < SRC; s++) m = fmaxf(m, sm.a.sc[s]);
            float sum = 0.f;
            for (int s = 0; s < SRC; s++) { float e = expf(sm.a.sc[s] - m); sm.a.sc[s] = e; sum += e; }
            sm.a.isum = 1.f / sum;
        }
        __syncthreads();
        const float isum = sm.a.isum;
        float* dst = (which ? g_c : g_h) + (size_t)bi * HID;
        for (int d = tid; d < HID; d += 256) {
            float acc = 0.f;
#pragma unroll 10
            for (int s = 0; s < SRC; s++) acc += sm.a.sc[s] * enc[((size_t)s * BATCH + bi) * HID + d];
            dst[d] = acc * isum + sm.a.vv[d];
        }
    }

    // ================= last-block-done final argmax ===========================
    __threadfence();
    __syncthreads();
    if (tid == 0) {
        int old = atomicAdd(&g_done, 1);
        s_last = (old == (int)gridDim.x - 1);
    }
    __syncthreads();
    if (s_last) {
        const int b = tid & 63, grp = tid >> 6;
        float bv = NEG_INF; int bx = 0x7fffffff;
        for (int p = grp; p < NLOG; p += 4) {
            float v = g_pmax[p * 64 + b];
            int  ix = g_pidx[p * 64 + b];
            if (v > bv || (v == bv && ix < bx)) { bv = v; bx = ix; }
        }
        __syncthreads();   // all threads past union reuse of sm before writing sm.m
        sm.m.sv[tid] = bv; sm.m.si[tid] = bx;
        __syncthreads();
        if (tid < 64) {
            for (int g = 1; g < 4; g++) {
                float v = sm.m.sv[tid + 64 * g];
                int  ix = sm.m.si[tid + 64 * g];
                if (v > bv || (v == bv && ix < bx)) { bv = v; bx = ix; }
            }
            g_tok[b] = bx;
            if (write_tok) out_tok[b * STEPS + step] = (float)bx;
        }
        if (tid == 0) g_done = 0;
    }
}

// ---------------- launch: 1 init + 31 x (lstm, fused) -----------------------
extern "C" void kernel_launch(void* const* d_in, const int* in_sizes, int n_in,
                              void* d_out, int out_size) {
    const float* embed   = (const float*)d_in[0];
    const float* fc_bias = (const float*)d_in[1];
    const float* w_ih    = (const float*)d_in[2];
    const float* w_hh    = (const float*)d_in[3];
    const float* b_ih    = (const float*)d_in[4];
    const float* b_hh    = (const float*)d_in[5];
    const float* enc     = (const float*)d_in[6];
    const float* h0      = (const float*)d_in[7];
    const float* c0      = (const float*)d_in[8];
    const int*   t0      = (const int*)d_in[9];
    float* out = (float*)d_out;

    const long long LT = (long long)STEPS * BATCH * VOCAB;  // 99,200,000
    int write_tok = ((long long)out_size >= LT + (long long)BATCH * STEPS) ? 1 : 0;
    float* out_tok = out + LT;

    k_init<<<32, 256>>>(h0, c0, t0);
    for (int t = 0; t < STEPS; t++) {
        k_lstm<<<128, 512>>>(embed, w_ih, w_hh, b_ih, b_hh);
        k_fused<<<NLOG + 128, 256>>>(embed, fc_bias, enc,
                                     out + (long long)t * BATCH * VOCAB,
                                     out_tok, t, write_tok);
    }
}